// round 11
// baseline (speedup 1.0000x reference)
#include <cuda_runtime.h>
#include <cuda_bf16.h>
#include <math.h>

#define Bsz  512
#define NTOK 20
#define Dm   128
#define Hh   8
#define FFd  512
#define HIDd 512

// ---------------- device scratch (no cudaMalloc allowed) ----------------
__device__ float g_x[Bsz*NTOK*Dm];       // compacted embeddings (encoder input)
__device__ float g_crd[Bsz*NTOK*2];      // compacted coords
__device__ int   g_nidx[Bsz*NTOK];       // compacted node indices
__device__ float g_buf1[Bsz*NTOK*Dm];    // post-MHA residual (pre-bn1)
__device__ float g_buf2[Bsz*NTOK*Dm];    // post-FFN residual (pre-bn2)
__device__ float g_psumT[Dm*Bsz];        // transposed BN partials [feature][block]
__device__ float g_psqT[Dm*Bsz];
__device__ float g_bn1s[Dm], g_bn1h[Dm], g_bn2s[Dm], g_bn2h[Dm];
__device__ float g_ctxq[Dm];             // (W_ph @ W_step), batch-independent
__device__ float g_cph[HIDd];            // bc1 + W_ph @ Wc1[128:384,:]
__device__ float g_prev[Bsz*2];
__device__ float g_first[Bsz*2];
__device__ int   g_tours[Bsz*NTOK];
__device__ int   g_cntA = 0;             // mha tail counter
__device__ int   g_cntB = 0;             // ffn tail counter

// packed weights (filled by k_pack each call)
__device__ float4 g_wqkvp[3*128*128];    // [l][d][tid] -> (q,k,v,0), tid=h*16+kd
__device__ float4 g_wop[3*32*128];       // [l][j4][tid] -> Wo[4j4+r][tid]
__device__ float4 g_w1p[3*128*128];      // [l][d][tid] -> W1[d][tid+128r]
__device__ float4 g_w2p[3*128*128];      // [l][j4][tid] -> W2[4j4+r][tid]
__device__ float4 g_wnp[128*128];        // [d][tid] -> W_node[d][tid+128r], r<3
__device__ float4 g_wfp[32*128];         // [k4][tid] -> W_fixed[4k4+r][tid]
__device__ float4 g_woutp[32*128];       // [k4][tid] -> W_out[4k4+r][tid]
__device__ float4 g_wc1p[32*512];        // [k4][j] -> Wc1[4k4+r][j]

// ---------------- one-shot weight packing ----------------
__global__ void k_pack(const float* __restrict__ Wq, const float* __restrict__ Wk,
                       const float* __restrict__ Wv, const float* __restrict__ Wo,
                       const float* __restrict__ W1, const float* __restrict__ W2,
                       const float* __restrict__ Wn, const float* __restrict__ Wf,
                       const float* __restrict__ Wou, const float* __restrict__ Wc1)
{
    int idx = blockIdx.x*blockDim.x + threadIdx.x;
    if (idx < 49152) {                       // wqkvp
        int l = idx >> 14, rem = idx & 16383, d = rem >> 7, t = rem & 127;
        int h = t >> 4, kd = t & 15;
        int s = l*16384 + h*2048 + d*16 + kd;
        g_wqkvp[idx] = make_float4(Wq[s], Wk[s], Wv[s], 0.f);
        return;
    }
    idx -= 49152;
    if (idx < 12288) {                       // wop
        int l = idx >> 12, rem = idx & 4095;
        const float* s = Wo + l*16384 + (rem >> 7)*512 + (rem & 127);
        g_wop[idx] = make_float4(s[0], s[128], s[256], s[384]);
        return;
    }
    idx -= 12288;
    if (idx < 49152) {                       // w1p
        int l = idx >> 14, rem = idx & 16383;
        const float* s = W1 + l*65536 + (rem >> 7)*512 + (rem & 127);
        g_w1p[idx] = make_float4(s[0], s[128], s[256], s[384]);
        return;
    }
    idx -= 49152;
    if (idx < 49152) {                       // w2p
        int l = idx >> 14, rem = idx & 16383;
        const float* s = W2 + l*65536 + (rem >> 7)*512 + (rem & 127);
        g_w2p[idx] = make_float4(s[0], s[128], s[256], s[384]);
        return;
    }
    idx -= 49152;
    if (idx < 16384) {                       // wnp
        const float* s = Wn + (idx >> 7)*384 + (idx & 127);
        g_wnp[idx] = make_float4(s[0], s[128], s[256], 0.f);
        return;
    }
    idx -= 16384;
    if (idx < 4096) {                        // wfp
        const float* s = Wf + (idx >> 7)*512 + (idx & 127);
        g_wfp[idx] = make_float4(s[0], s[128], s[256], s[384]);
        return;
    }
    idx -= 4096;
    if (idx < 4096) {                        // woutp
        const float* s = Wou + (idx >> 7)*512 + (idx & 127);
        g_woutp[idx] = make_float4(s[0], s[128], s[256], s[384]);
        return;
    }
    idx -= 4096;
    if (idx < 16384) {                       // wc1p
        const float* s = Wc1 + (idx >> 9)*2048 + (idx & 511);
        g_wc1p[idx] = make_float4(s[0], s[512], s[1024], s[1536]);
    }
}

// ---------------- x = coords@Wi + bi ; init crd / node_idx ----------------
__global__ void k_embed(const float* __restrict__ coords,
                        const float* __restrict__ Wi,
                        const float* __restrict__ bi)
{
    int b = blockIdx.x, tid = threadIdx.x;
    float w0 = Wi[tid], w1 = Wi[Dm + tid], bb = bi[tid];
    const float* cb = coords + b*NTOK*2;
    float* xb = g_x + (size_t)b*NTOK*Dm;
    #pragma unroll
    for (int t = 0; t < NTOK; t++)
        xb[t*Dm + tid] = cb[2*t]*w0 + cb[2*t+1]*w1 + bb;
    if (tid < NTOK*2) g_crd[b*NTOK*2 + tid] = cb[tid];
    if (tid < NTOK)   g_nidx[b*NTOK + tid] = tid;
}

// ---------------- constants: ctx_q and value-head placeholder term ----------------
__global__ void k_setup(const float* __restrict__ W_ph, const float* __restrict__ W_step,
                        const float* __restrict__ Wc1,  const float* __restrict__ bc1)
{
    __shared__ float ph[2*Dm];
    int tid = threadIdx.x;                 // 512 threads
    if (tid < 2*Dm) ph[tid] = W_ph[tid];
    __syncthreads();
    if (tid < Dm) {
        float a = 0.f;
        for (int k = 0; k < 2*Dm; k++) a += ph[k]*W_step[k*Dm + tid];
        g_ctxq[tid] = a;
    }
    float c = bc1[tid];
    for (int k = 0; k < 2*Dm; k++) c += ph[k]*Wc1[(Dm + k)*HIDd + tid];
    g_cph[tid] = c;
}

// ---------------- fused BN stat tail: last arriving block reduces ----------------
__device__ __forceinline__ void bn_stats_tail(int b, int tid, int n,
        const float* __restrict__ gam, const float* __restrict__ bet,
        float* bns, float* bnh, int* cnt, float psum, float psq)
{
    g_psumT[tid*Bsz + b] = psum;
    g_psqT[tid*Bsz + b] = psq;
    __threadfence();
    __shared__ int s_last;
    if (tid == 0) s_last = (atomicAdd(cnt, 1) == Bsz - 1) ? 1 : 0;
    __syncthreads();
    if (!s_last) return;
    const float4* ps4 = (const float4*)(g_psumT + tid*Bsz);
    const float4* pq4 = (const float4*)(g_psqT + tid*Bsz);
    float s0=0.f,s1=0.f,s2=0.f,s3=0.f,q0=0.f,q1=0.f,q2=0.f,q3=0.f;
    #pragma unroll 4
    for (int j = 0; j < Bsz/4; j++) {
        float4 a = __ldcg(ps4 + j);
        float4 c = __ldcg(pq4 + j);
        s0 += a.x; s1 += a.y; s2 += a.z; s3 += a.w;
        q0 += c.x; q1 += c.y; q2 += c.z; q3 += c.w;
    }
    float s = (s0+s1)+(s2+s3);
    float q = (q0+q1)+(q2+q3);
    float inv = 1.f / ((float)Bsz * (float)n);
    float m = s*inv;
    float v = q*inv - m*m;
    float scl = gam[tid] / sqrtf(v + 1e-5f);
    bns[tid] = scl;
    bnh[tid] = bet[tid] - m*scl;
    if (tid == 0) *cnt = 0;
}

// ---------------- MHA + residual + fused BN1 stats ----------------
// src==0: input = g_x (raw). src==1: input = bn2(g_buf2).
__global__ void __launch_bounds__(128) k_mha(int src, int l,
        const float* __restrict__ gam, const float* __restrict__ bet, int n)
{
    __shared__ __align__(16) float xs[24][Dm];
    __shared__ __align__(16) float qs[NTOK*Dm];
    __shared__ __align__(16) float ks2[NTOK*Dm];
    __shared__ __align__(16) float vs[NTOK*Dm];
    int b = blockIdx.x, tid = threadIdx.x;
    const float* xin = (src ? g_buf2 : g_x) + (size_t)b*NTOK*Dm;
    float sc = src ? g_bn2s[tid] : 1.f;
    float sh = src ? g_bn2h[tid] : 0.f;
    #pragma unroll
    for (int t = 0; t < 24; t++)
        xs[t][tid] = (t < n) ? (xin[t*Dm + tid]*sc + sh) : 0.f;
    __syncthreads();

    // ---- fused QKV projection (vectorized) ----
    {
        const float4* wp = g_wqkvp + l*16384 + tid;
        const float4 (*xs4)[32] = (const float4 (*)[32])xs;
        for (int t0 = 0; t0 < n; t0 += 8) {
            float aq[8], ak[8], av[8];
            #pragma unroll
            for (int u = 0; u < 8; u++) { aq[u]=0.f; ak[u]=0.f; av[u]=0.f; }
            for (int d4 = 0; d4 < 32; d4++) {
                float4 xv[8];
                #pragma unroll
                for (int u = 0; u < 8; u++) xv[u] = xs4[t0+u][d4];
                #pragma unroll
                for (int r = 0; r < 4; r++) {
                    float4 w = wp[(d4*4 + r)*128];
                    #pragma unroll
                    for (int u = 0; u < 8; u++) {
                        float x = (r==0)?xv[u].x:(r==1)?xv[u].y:(r==2)?xv[u].z:xv[u].w;
                        aq[u] += x*w.x; ak[u] += x*w.y; av[u] += x*w.z;
                    }
                }
            }
            #pragma unroll
            for (int u = 0; u < 8; u++) {
                int t = t0 + u;
                if (t < n) {
                    qs[t*Dm + tid] = aq[u];
                    ks2[t*Dm + tid] = ak[u];
                    vs[t*Dm + tid] = av[u];
                }
            }
        }
    }
    __syncthreads();

    // ---- attention: one (t,h) pair per thread, <=2 iterations ----
    int npairs = n * Hh;
    float outr[2][16];
    {
        const float4* q4 = (const float4*)qs;
        const float4* k4 = (const float4*)ks2;
        const float4* v4 = (const float4*)vs;
        #pragma unroll
        for (int it = 0; it < 2; it++) {
            int pair = tid + it*128;
            if (pair < npairs) {
                int t = pair >> 3, hh = pair & 7;
                int qb = t*32 + hh*4, kb = hh*4;
                float4 q0 = q4[qb], q1 = q4[qb+1], q2 = q4[qb+2], q3 = q4[qb+3];
                float s[NTOK];
                float mx = -1e30f;
                #pragma unroll
                for (int m = 0; m < NTOK; m++) if (m < n) {
                    float4 a0 = k4[m*32+kb],   a1 = k4[m*32+kb+1];
                    float4 a2 = k4[m*32+kb+2], a3 = k4[m*32+kb+3];
                    float p = q0.x*a0.x + q0.y*a0.y + q0.z*a0.z + q0.w*a0.w
                            + q1.x*a1.x + q1.y*a1.y + q1.z*a1.z + q1.w*a1.w
                            + q2.x*a2.x + q2.y*a2.y + q2.z*a2.z + q2.w*a2.w
                            + q3.x*a3.x + q3.y*a3.y + q3.z*a3.z + q3.w*a3.w;
                    p *= 0.25f;
                    s[m] = p;
                    mx = fmaxf(mx, p);
                }
                float ssum = 0.f;
                #pragma unroll
                for (int m = 0; m < NTOK; m++) if (m < n) {
                    float e = expf(s[m]-mx); s[m] = e; ssum += e;
                }
                float inv = 1.f/ssum;
                float o[16];
                #pragma unroll
                for (int j = 0; j < 16; j++) o[j] = 0.f;
                #pragma unroll
                for (int m = 0; m < NTOK; m++) if (m < n) {
                    float a = s[m]*inv;
                    float4 va = v4[m*32+kb],   vb = v4[m*32+kb+1];
                    float4 vc = v4[m*32+kb+2], vd = v4[m*32+kb+3];
                    o[0] += a*va.x;  o[1] += a*va.y;  o[2] += a*va.z;  o[3] += a*va.w;
                    o[4] += a*vb.x;  o[5] += a*vb.y;  o[6] += a*vb.z;  o[7] += a*vb.w;
                    o[8] += a*vc.x;  o[9] += a*vc.y;  o[10]+= a*vc.z;  o[11]+= a*vc.w;
                    o[12]+= a*vd.x;  o[13]+= a*vd.y;  o[14]+= a*vd.z;  o[15]+= a*vd.w;
                }
                #pragma unroll
                for (int j = 0; j < 16; j++) outr[it][j] = o[j];
            }
        }
    }
    __syncthreads();
    // write attention output into qs (plain [t][j] layout), float4 stores
    {
        float4* aw = (float4*)qs;
        #pragma unroll
        for (int it = 0; it < 2; it++) {
            int pair = tid + it*128;
            if (pair < npairs) {
                int t = pair >> 3, hh = pair & 7;
                #pragma unroll
                for (int j4 = 0; j4 < 4; j4++)
                    aw[t*32 + hh*4 + j4] = make_float4(outr[it][j4*4], outr[it][j4*4+1],
                                                      outr[it][j4*4+2], outr[it][j4*4+3]);
            }
        }
    }
    __syncthreads();

    // ---- output projection + residual + BN partials ----
    float psum = 0.f, psq = 0.f;
    {
        const float4* wo4 = g_wop + l*4096 + tid;
        const float4* a4 = (const float4*)qs;
        for (int t0 = 0; t0 < n; t0 += 8) {
            float acc[8];
            int base[8];
            #pragma unroll
            for (int u = 0; u < 8; u++) {
                acc[u] = 0.f;
                int t = t0 + u;
                base[u] = (t < n ? t : n-1) * 32;
            }
            for (int j4 = 0; j4 < 32; j4++) {
                float4 w = wo4[j4*128];
                #pragma unroll
                for (int u = 0; u < 8; u++) {
                    float4 a = a4[base[u] + j4];
                    acc[u] += a.x*w.x + a.y*w.y + a.z*w.z + a.w*w.w;
                }
            }
            #pragma unroll
            for (int u = 0; u < 8; u++) {
                int t = t0 + u;
                if (t < n) {
                    float y = xs[t][tid] + acc[u];
                    g_buf1[(size_t)b*NTOK*Dm + t*Dm + tid] = y;
                    psum += y; psq += y*y;
                }
            }
        }
    }
    bn_stats_tail(b, tid, n, gam, bet, g_bn1s, g_bn1h, &g_cntA, psum, psq);
}

// ---------------- FFN + residual + fused BN2 stats (input = bn1(g_buf1)) ----------------
__global__ void __launch_bounds__(128) k_ffn(int l,
        const float* __restrict__ b1, const float* __restrict__ b2,
        const float* __restrict__ gam, const float* __restrict__ bet, int n)
{
    __shared__ __align__(16) float us[24][Dm];
    __shared__ __align__(16) float f1s[8][FFd];
    int b = blockIdx.x, tid = threadIdx.x;
    float s1 = g_bn1s[tid], h1 = g_bn1h[tid];
    #pragma unroll
    for (int t = 0; t < 24; t++)
        us[t][tid] = (t < n) ? (g_buf1[(size_t)b*NTOK*Dm + t*Dm + tid]*s1 + h1) : 0.f;
    float bv0 = b1[tid], bv1 = b1[128+tid], bv2 = b1[256+tid], bv3 = b1[384+tid];
    float b2v = b2[tid];
    float psum = 0.f, psq = 0.f;
    __syncthreads();

    const float4* w1p = g_w1p + l*16384 + tid;
    const float4* w2p = g_w2p + l*16384 + tid;
    const float4 (*us4)[32] = (const float4 (*)[32])us;

    for (int t0 = 0; t0 < n; t0 += 8) {
        // stage 1: f1 = relu(u@W1 + b1)
        float a0[8], a1[8], a2[8], a3[8];
        #pragma unroll
        for (int u = 0; u < 8; u++) { a0[u]=bv0; a1[u]=bv1; a2[u]=bv2; a3[u]=bv3; }
        for (int d4 = 0; d4 < 32; d4++) {
            float4 xv[8];
            #pragma unroll
            for (int u = 0; u < 8; u++) xv[u] = us4[t0+u][d4];
            #pragma unroll
            for (int r = 0; r < 4; r++) {
                float4 w = w1p[(d4*4 + r)*128];
                #pragma unroll
                for (int u = 0; u < 8; u++) {
                    float x = (r==0)?xv[u].x:(r==1)?xv[u].y:(r==2)?xv[u].z:xv[u].w;
                    a0[u] += x*w.x; a1[u] += x*w.y; a2[u] += x*w.z; a3[u] += x*w.w;
                }
            }
        }
        #pragma unroll
        for (int u = 0; u < 8; u++) {
            f1s[u][tid      ] = fmaxf(a0[u], 0.f);
            f1s[u][tid + 128] = fmaxf(a1[u], 0.f);
            f1s[u][tid + 256] = fmaxf(a2[u], 0.f);
            f1s[u][tid + 384] = fmaxf(a3[u], 0.f);
        }
        __syncthreads();
        // stage 2: f2 = f1@W2 + b2
        float c[8];
        #pragma unroll
        for (int u = 0; u < 8; u++) c[u] = b2v;
        for (int j4 = 0; j4 < 128; j4++) {
            float4 w = w2p[j4*128];
            #pragma unroll
            for (int u = 0; u < 8; u++) {
                float4 f = ((const float4*)f1s[u])[j4];
                c[u] += f.x*w.x + f.y*w.y + f.z*w.z + f.w*w.w;
            }
        }
        #pragma unroll
        for (int u = 0; u < 8; u++) {
            int t = t0 + u;
            if (t < n) {
                float y = us[t][tid] + c[u];
                g_buf2[(size_t)b*NTOK*Dm + t*Dm + tid] = y;
                psum += y; psq += y*y;
            }
        }
        __syncthreads();
    }
    bn_stats_tail(b, tid, n, gam, bet, g_bn2s, g_bn2h, &g_cntB, psum, psq);
}

// ---------------- decode step ----------------
__global__ void __launch_bounds__(128) k_decode(int i, int n,
        const float* __restrict__ Wc2, const float* __restrict__ bc2,
        float* __restrict__ out)
{
    __shared__ __align__(16) float es[24][Dm];
    __shared__ __align__(16) float ps[NTOK*384];   // gK | gV | lK per token
    __shared__ __align__(16) float gms[Dm];
    __shared__ __align__(16) float glim[Dm];
    __shared__ float qv[Dm], go[Dm];
    __shared__ float logit_s[NTOK];
    __shared__ float red[128];
    __shared__ int   sel_s;
    __shared__ float lp_s;
    int b = blockIdx.x, tid = threadIdx.x;

    // E = bn2(buf2); g_mean
    float s2 = g_bn2s[tid], h2 = g_bn2h[tid];
    float gsum = 0.f;
    #pragma unroll
    for (int t = 0; t < 24; t++) {
        float e = (t < n) ? (g_buf2[(size_t)b*NTOK*Dm + t*Dm + tid]*s2 + h2) : 0.f;
        es[t][tid] = e; gsum += e;
    }
    gms[tid] = gsum / (float)n;
    __syncthreads();

    const float4* gms4 = (const float4*)gms;

    // q = g_mean @ W_fixed + ctx_q  (vectorized)
    {
        float qa = g_ctxq[tid];
        const float4* wf = g_wfp + tid;
        for (int k4 = 0; k4 < 32; k4++) {
            float4 g = gms4[k4];
            float4 w = wf[k4*128];
            qa += g.x*w.x + g.y*w.y + g.z*w.z + g.w*w.w;
        }
        qv[tid] = qa;
    }

    // P = E @ W_node  (n x 384), packed
    {
        const float4* wn = g_wnp + tid;
        const float4 (*es4)[32] = (const float4 (*)[32])es;
        for (int t0 = 0; t0 < n; t0 += 8) {
            float a0[8], a1[8], a2[8];
            #pragma unroll
            for (int u = 0; u < 8; u++) { a0[u]=0.f; a1[u]=0.f; a2[u]=0.f; }
            for (int d4 = 0; d4 < 32; d4++) {
                float4 xv[8];
                #pragma unroll
                for (int u = 0; u < 8; u++) xv[u] = es4[t0+u][d4];
                #pragma unroll
                for (int r = 0; r < 4; r++) {
                    float4 w = wn[(d4*4 + r)*128];
                    #pragma unroll
                    for (int u = 0; u < 8; u++) {
                        float x = (r==0)?xv[u].x:(r==1)?xv[u].y:(r==2)?xv[u].z:xv[u].w;
                        a0[u] += x*w.x; a1[u] += x*w.y; a2[u] += x*w.z;
                    }
                }
            }
            #pragma unroll
            for (int u = 0; u < 8; u++) {
                int t = t0 + u;
                if (t < n) {
                    ps[t*384 + tid      ] = a0[u];
                    ps[t*384 + tid + 128] = a1[u];
                    ps[t*384 + tid + 256] = a2[u];
                }
            }
        }
    }
    __syncthreads();

    // glimpse attention: thread tid = (h, kd)
    {
        float qh = qv[tid];
        float sc[NTOK];
        float mx = -1e30f;
        #pragma unroll
        for (int m = 0; m < NTOK; m++) if (m < n) {
            float p = qh * ps[m*384 + tid];
            #pragma unroll
            for (int o = 8; o > 0; o >>= 1) p += __shfl_xor_sync(0xffffffffu, p, o, 16);
            p *= 0.25f;
            sc[m] = p;
            mx = fmaxf(mx, p);
        }
        float ssum = 0.f;
        #pragma unroll
        for (int m = 0; m < NTOK; m++) if (m < n) {
            float e = expf(sc[m]-mx); sc[m] = e; ssum += e;
        }
        float gl = 0.f;
        #pragma unroll
        for (int m = 0; m < NTOK; m++) if (m < n)
            gl += sc[m]*ps[m*384 + 128 + tid];
        glim[tid] = gl/ssum;
    }
    __syncthreads();
    // glimpse @ W_out (vectorized)
    {
        float g = 0.f;
        const float4* wo = g_woutp + tid;
        const float4* gl4 = (const float4*)glim;
        for (int k4 = 0; k4 < 32; k4++) {
            float4 gv = gl4[k4];
            float4 w = wo[k4*128];
            g += gv.x*w.x + gv.y*w.y + gv.z*w.z + gv.w*w.w;
        }
        go[tid] = g;
    }
    __syncthreads();
    // logits per token (one warp per token, strided)
    {
        int w = tid >> 5, lane = tid & 31;
        for (int t = w; t < n; t += 4) {
            float p = 0.f;
            #pragma unroll
            for (int r = 0; r < 4; r++)
                p += go[lane + 32*r]*ps[t*384 + 256 + lane + 32*r];
            #pragma unroll
            for (int o = 16; o > 0; o >>= 1) p += __shfl_xor_sync(0xffffffffu, p, o);
            if (lane == 0)
                logit_s[t] = tanhf(p * 0.08838834764831845f) * 10.f;
        }
    }
    __syncthreads();
    // log_softmax + argmax (first-max tie rule) on warp 0
    if (tid < 32) {
        float v = (tid < n) ? logit_s[tid] : -1e30f;
        float m = v;
        #pragma unroll
        for (int o = 16; o > 0; o >>= 1) m = fmaxf(m, __shfl_xor_sync(0xffffffffu, m, o));
        int idx = (tid < n && v == m) ? tid : (1 << 30);
        #pragma unroll
        for (int o = 16; o > 0; o >>= 1) idx = min(idx, __shfl_xor_sync(0xffffffffu, idx, o));
        float e = (tid < n) ? expf(v - m) : 0.f;
        float se = e;
        #pragma unroll
        for (int o = 16; o > 0; o >>= 1) se += __shfl_xor_sync(0xffffffffu, se, o);
        if (tid == 0) { sel_s = idx; lp_s = logit_s[idx] - m - logf(se); }
    }
    __syncthreads();
    int sel = sel_s;

    // value head: relu(g_mean @ Wc1[:128,:] + cph) @ Wc2  (vectorized)
    {
        float part = 0.f;
        #pragma unroll
        for (int r = 0; r < 4; r++) {
            int j = tid + 128*r;
            float acc = g_cph[j];
            const float4* wc = g_wc1p + j;
            for (int k4 = 0; k4 < 32; k4++) {
                float4 g = gms4[k4];
                float4 w = wc[k4*512];
                acc += g.x*w.x + g.y*w.y + g.z*w.z + g.w*w.w;
            }
            part += fmaxf(acc, 0.f)*Wc2[j];
        }
        red[tid] = part;
    }
    __syncthreads();
    for (int st = 64; st > 0; st >>= 1) {
        if (tid < st) red[tid] += red[tid+st];
        __syncthreads();
    }

    // outputs + state (thread 0)
    if (tid == 0) {
        float val = red[0] + bc2[0];
        float cx = g_crd[b*NTOK*2 + sel*2], cy = g_crd[b*NTOK*2 + sel*2 + 1];
        float ir = 0.f;
        if (i == 0) {
            g_first[2*b] = cx; g_first[2*b+1] = cy;
        } else {
            float dx = cx - g_prev[2*b], dy = cy - g_prev[2*b+1];
            ir = -sqrtf(dx*dx + dy*dy);
        }
        g_prev[2*b] = cx; g_prev[2*b+1] = cy;
        int node = g_nidx[b*NTOK + sel];
        g_tours[b*NTOK + i] = node;
        out[             b*NTOK + i] = lp_s;        // log_ps
        out[Bsz*NTOK   + b*NTOK + i] = ir;          // irs
        out[2*Bsz*NTOK + b*NTOK + i] = val;         // vals
        out[3*Bsz*NTOK + 2*Bsz + b*NTOK + i] = (float)node;  // tours
    }
    __syncthreads();

    // compaction (stable removal of sel)
    if (i < NTOK-1) {
        for (int t = sel; t < n-1; t++)
            g_x[(size_t)b*NTOK*Dm + t*Dm + tid] = g_x[(size_t)b*NTOK*Dm + (t+1)*Dm + tid];
        if (tid < 2)
            for (int t = sel; t < n-1; t++)
                g_crd[b*NTOK*2 + t*2 + tid] = g_crd[b*NTOK*2 + (t+1)*2 + tid];
        if (tid == 0)
            for (int t = sel; t < n-1; t++)
                g_nidx[b*NTOK + t] = g_nidx[b*NTOK + t+1];
    }
}

// ---------------- final: tour cost + reward_final ----------------
__global__ void k_final(const float* __restrict__ coords, float* __restrict__ out)
{
    int b = blockIdx.x*blockDim.x + threadIdx.x;
    if (b >= Bsz) return;
    const int* tb = g_tours + b*NTOK;
    const float* cb = coords + b*NTOK*2;
    float x0 = cb[tb[0]*2], y0 = cb[tb[0]*2 + 1];
    float px = x0, py = y0;
    float cost = 0.f;
    for (int t = 1; t < NTOK; t++) {
        float x = cb[tb[t]*2], y = cb[tb[t]*2 + 1];
        float dx = x - px, dy = y - py;
        cost += sqrtf(dx*dx + dy*dy);
        px = x; py = y;
    }
    {
        float dx = x0 - px, dy = y0 - py;
        cost += sqrtf(dx*dx + dy*dy);
    }
    out[3*Bsz*NTOK + b] = cost;                       // cost
    float fx = g_first[2*b] - g_prev[2*b];
    float fy = g_first[2*b+1] - g_prev[2*b+1];
    out[3*Bsz*NTOK + Bsz + b] = -sqrtf(fx*fx + fy*fy); // reward_final
}

// ---------------- host ----------------
extern "C" void kernel_launch(void* const* d_in, const int* in_sizes, int n_in,
                              void* d_out, int out_size)
{
    const float* coords  = (const float*)d_in[0];
    const float* Wi      = (const float*)d_in[1];
    const float* bi      = (const float*)d_in[2];
    const float* W_ph    = (const float*)d_in[3];
    const float* eWq     = (const float*)d_in[4];
    const float* eWk     = (const float*)d_in[5];
    const float* eWv     = (const float*)d_in[6];
    const float* eWo     = (const float*)d_in[7];
    const float* eg1     = (const float*)d_in[8];
    const float* eb1     = (const float*)d_in[9];
    const float* effW1   = (const float*)d_in[10];
    const float* effb1   = (const float*)d_in[11];
    const float* effW2   = (const float*)d_in[12];
    const float* effb2   = (const float*)d_in[13];
    const float* eg2     = (const float*)d_in[14];
    const float* eb2     = (const float*)d_in[15];
    const float* W_node  = (const float*)d_in[16];
    const float* W_fixed = (const float*)d_in[17];
    const float* W_step  = (const float*)d_in[18];
    const float* W_out   = (const float*)d_in[19];
    const float* Wc1     = (const float*)d_in[20];
    const float* bc1     = (const float*)d_in[21];
    const float* Wc2     = (const float*)d_in[22];
    const float* bc2     = (const float*)d_in[23];
    float* out = (float*)d_out;

    k_pack<<<784, 256>>>(eWq, eWk, eWv, eWo, effW1, effW2,
                         W_node, W_fixed, W_out, Wc1);
    k_embed<<<Bsz, 128>>>(coords, Wi, bi);
    k_setup<<<1, 512>>>(W_ph, W_step, Wc1, bc1);

    for (int i = 0; i < NTOK; i++) {
        int n = NTOK - i;
        for (int l = 0; l < 3; l++) {
            k_mha<<<Bsz, 128>>>(l == 0 ? 0 : 1, l, eg1 + l*Dm, eb1 + l*Dm, n);
            k_ffn<<<Bsz, 128>>>(l, effb1 + l*FFd, effb2 + l*Dm,
                                eg2 + l*Dm, eb2 + l*Dm, n);
        }
        k_decode<<<Bsz, 128>>>(i, n, Wc2, bc2, out);
    }
    k_final<<<2, 256>>>(coords, out);
}

// round 12
// speedup vs baseline: 1.1074x; 1.1074x over previous
#include <cuda_runtime.h>
#include <cuda_bf16.h>
#include <math.h>

#define Bsz  512
#define NTOK 20
#define Dm   128
#define Hh   8
#define FFd  512
#define HIDd 512

// ---------------- device scratch (no cudaMalloc allowed) ----------------
__device__ float g_x[Bsz*NTOK*Dm];
__device__ float g_crd[Bsz*NTOK*2];
__device__ int   g_nidx[Bsz*NTOK];
__device__ float g_buf1[Bsz*NTOK*Dm];
__device__ float g_buf2[Bsz*NTOK*Dm];
__device__ float g_psumT[Dm*Bsz];        // [feature][block]
__device__ float g_psqT[Dm*Bsz];
__device__ float g_bn1s[Dm], g_bn1h[Dm], g_bn2s[Dm], g_bn2h[Dm];
__device__ float g_ctxq[Dm];
__device__ float g_cph[HIDd];
__device__ float g_prev[Bsz*2];
__device__ float g_first[Bsz*2];
__device__ int   g_tours[Bsz*NTOK];
__device__ int   g_cntA = 0;
__device__ int   g_cntB = 0;

// packed weights
__device__ float4 g_wqkvp[3*128*128];    // [l][d][f] -> (q,k,v,0)
__device__ float4 g_wop[3*32*128];       // [l][j4][f] -> Wo[4j4+r][f]
__device__ float4 g_w1p[3*128*128];      // [l][d][f] -> W1[d][f+128r]
__device__ float4 g_w2p[3*128*128];      // [l][j4][f] -> W2[4j4+r][f]
__device__ float4 g_wnp[128*128];        // [d][f] -> W_node[d][f+128r], r<3
__device__ float4 g_wfp[32*128];         // [k4][f] -> W_fixed[4k4+r][f]
__device__ float4 g_woutp[32*128];       // [k4][f] -> W_out[4k4+r][f]
__device__ float4 g_wc1p[32*512];        // [k4][j] -> Wc1[4k4+r][j]

// ---------------- one-shot weight packing ----------------
__global__ void k_pack(const float* __restrict__ Wq, const float* __restrict__ Wk,
                       const float* __restrict__ Wv, const float* __restrict__ Wo,
                       const float* __restrict__ W1, const float* __restrict__ W2,
                       const float* __restrict__ Wn, const float* __restrict__ Wf,
                       const float* __restrict__ Wou, const float* __restrict__ Wc1)
{
    int idx = blockIdx.x*blockDim.x + threadIdx.x;
    if (idx < 49152) {
        int l = idx >> 14, rem = idx & 16383, d = rem >> 7, t = rem & 127;
        int h = t >> 4, kd = t & 15;
        int s = l*16384 + h*2048 + d*16 + kd;
        g_wqkvp[idx] = make_float4(Wq[s], Wk[s], Wv[s], 0.f);
        return;
    }
    idx -= 49152;
    if (idx < 12288) {
        int l = idx >> 12, rem = idx & 4095;
        const float* s = Wo + l*16384 + (rem >> 7)*512 + (rem & 127);
        g_wop[idx] = make_float4(s[0], s[128], s[256], s[384]);
        return;
    }
    idx -= 12288;
    if (idx < 49152) {
        int l = idx >> 14, rem = idx & 16383;
        const float* s = W1 + l*65536 + (rem >> 7)*512 + (rem & 127);
        g_w1p[idx] = make_float4(s[0], s[128], s[256], s[384]);
        return;
    }
    idx -= 49152;
    if (idx < 49152) {
        int l = idx >> 14, rem = idx & 16383;
        const float* s = W2 + l*65536 + (rem >> 7)*512 + (rem & 127);
        g_w2p[idx] = make_float4(s[0], s[128], s[256], s[384]);
        return;
    }
    idx -= 49152;
    if (idx < 16384) {
        const float* s = Wn + (idx >> 7)*384 + (idx & 127);
        g_wnp[idx] = make_float4(s[0], s[128], s[256], 0.f);
        return;
    }
    idx -= 16384;
    if (idx < 4096) {
        const float* s = Wf + (idx >> 7)*512 + (idx & 127);
        g_wfp[idx] = make_float4(s[0], s[128], s[256], s[384]);
        return;
    }
    idx -= 4096;
    if (idx < 4096) {
        const float* s = Wou + (idx >> 7)*512 + (idx & 127);
        g_woutp[idx] = make_float4(s[0], s[128], s[256], s[384]);
        return;
    }
    idx -= 4096;
    if (idx < 16384) {
        const float* s = Wc1 + (idx >> 9)*2048 + (idx & 511);
        g_wc1p[idx] = make_float4(s[0], s[512], s[1024], s[1536]);
    }
}

// ---------------- embed ----------------
__global__ void k_embed(const float* __restrict__ coords,
                        const float* __restrict__ Wi,
                        const float* __restrict__ bi)
{
    int b = blockIdx.x, tid = threadIdx.x;
    float w0 = Wi[tid], w1 = Wi[Dm + tid], bb = bi[tid];
    const float* cb = coords + b*NTOK*2;
    float* xb = g_x + (size_t)b*NTOK*Dm;
    #pragma unroll
    for (int t = 0; t < NTOK; t++)
        xb[t*Dm + tid] = cb[2*t]*w0 + cb[2*t+1]*w1 + bb;
    if (tid < NTOK*2) g_crd[b*NTOK*2 + tid] = cb[tid];
    if (tid < NTOK)   g_nidx[b*NTOK + tid] = tid;
}

// ---------------- constants ----------------
__global__ void k_setup(const float* __restrict__ W_ph, const float* __restrict__ W_step,
                        const float* __restrict__ Wc1,  const float* __restrict__ bc1)
{
    __shared__ float ph[2*Dm];
    int tid = threadIdx.x;   // 512
    if (tid < 2*Dm) ph[tid] = W_ph[tid];
    __syncthreads();
    if (tid < Dm) {
        float a = 0.f;
        for (int k = 0; k < 2*Dm; k++) a += ph[k]*W_step[k*Dm + tid];
        g_ctxq[tid] = a;
    }
    float c = bc1[tid];
    for (int k = 0; k < 2*Dm; k++) c += ph[k]*Wc1[(Dm + k)*HIDd + tid];
    g_cph[tid] = c;
}

// ---------------- fused BN stat tail, 256-thread version ----------------
// sA/sB are 256-float smem scratch. Thread layout (f = tid&127, g = tid>>7).
__device__ __forceinline__ void bn_stats_tail256(int b, int tid, int f, int g, int n,
        const float* __restrict__ gam, const float* __restrict__ bet,
        float* bns, float* bnh, int* cnt, float psum, float psq,
        float* sA, float* sB)
{
    sA[tid] = psum; sB[tid] = psq;
    __syncthreads();
    if (g == 0) {
        g_psumT[f*Bsz + b] = sA[f] + sA[f+128];
        g_psqT[f*Bsz + b]  = sB[f] + sB[f+128];
    }
    __threadfence();
    __shared__ int s_last;
    if (tid == 0) s_last = (atomicAdd(cnt, 1) == Bsz - 1) ? 1 : 0;
    __syncthreads();
    if (!s_last) return;
    // last block: 2 threads per feature, each sums 256 entries (64 float4)
    {
        const float4* ps4 = (const float4*)(g_psumT + f*Bsz) + g*64;
        const float4* pq4 = (const float4*)(g_psqT + f*Bsz) + g*64;
        float s0=0.f,s1=0.f,s2=0.f,s3=0.f,q0=0.f,q1=0.f,q2=0.f,q3=0.f;
        #pragma unroll 4
        for (int j = 0; j < 64; j++) {
            float4 a = __ldcg(ps4 + j);
            float4 c = __ldcg(pq4 + j);
            s0 += a.x; s1 += a.y; s2 += a.z; s3 += a.w;
            q0 += c.x; q1 += c.y; q2 += c.z; q3 += c.w;
        }
        sA[tid] = (s0+s1)+(s2+s3);
        sB[tid] = (q0+q1)+(q2+q3);
    }
    __syncthreads();
    if (g == 0) {
        float s = sA[f] + sA[f+128];
        float q = sB[f] + sB[f+128];
        float inv = 1.f / ((float)Bsz * (float)n);
        float m = s*inv;
        float v = q*inv - m*m;
        float scl = gam[f] / sqrtf(v + 1e-5f);
        bns[f] = scl;
        bnh[f] = bet[f] - m*scl;
    }
    if (tid == 0) *cnt = 0;
}

// ---------------- MHA + residual + fused BN1 stats (256 threads) ----------------
__global__ void __launch_bounds__(256, 4) k_mha(int src, int l,
        const float* __restrict__ gam, const float* __restrict__ bet, int n)
{
    __shared__ __align__(16) float xs[24][Dm];
    __shared__ __align__(16) float qs[NTOK*Dm];
    __shared__ __align__(16) float ks2[NTOK*Dm];
    __shared__ __align__(16) float vs[NTOK*Dm];
    __shared__ float sA[256], sB[256];
    int b = blockIdx.x, tid = threadIdx.x;
    int f = tid & 127, g = tid >> 7;
    const float* xin = (src ? g_buf2 : g_x) + (size_t)b*NTOK*Dm;
    float sc = src ? g_bn2s[f] : 1.f;
    float sh = src ? g_bn2h[f] : 0.f;
    #pragma unroll
    for (int t = g*12; t < g*12+12; t++)
        xs[t][f] = (t < n) ? (xin[t*Dm + f]*sc + sh) : 0.f;
    __syncthreads();

    int n0 = (n + 1) >> 1;
    int tstart = g ? n0 : 0;
    int tend   = g ? n  : n0;

    // ---- fused QKV projection: group handles its token half, chunks of 5 ----
    {
        const float4* wp = g_wqkvp + l*16384 + f;
        const float4 (*xs4)[32] = (const float4 (*)[32])xs;
        for (int t0 = tstart; t0 < tend; t0 += 5) {
            float aq[5], ak[5], av[5];
            int rb[5];
            #pragma unroll
            for (int u = 0; u < 5; u++) {
                aq[u]=0.f; ak[u]=0.f; av[u]=0.f;
                int t = t0 + u;
                rb[u] = (t < tend) ? t : (tend - 1);
            }
            for (int d4 = 0; d4 < 32; d4++) {
                float4 xv[5];
                #pragma unroll
                for (int u = 0; u < 5; u++) xv[u] = xs4[rb[u]][d4];
                #pragma unroll
                for (int r = 0; r < 4; r++) {
                    float4 w = wp[(d4*4 + r)*128];
                    #pragma unroll
                    for (int u = 0; u < 5; u++) {
                        float x = (r==0)?xv[u].x:(r==1)?xv[u].y:(r==2)?xv[u].z:xv[u].w;
                        aq[u] += x*w.x; ak[u] += x*w.y; av[u] += x*w.z;
                    }
                }
            }
            #pragma unroll
            for (int u = 0; u < 5; u++) {
                int t = t0 + u;
                if (t < tend) {
                    qs[t*Dm + f] = aq[u];
                    ks2[t*Dm + f] = ak[u];
                    vs[t*Dm + f] = av[u];
                }
            }
        }
    }
    __syncthreads();

    // ---- attention: one (t,h) pair per thread, single pass (n*8 <= 160 <= 256) ----
    int npairs = n * Hh;
    float outr[16];
    {
        const float4* q4 = (const float4*)qs;
        const float4* k4 = (const float4*)ks2;
        const float4* v4 = (const float4*)vs;
        if (tid < npairs) {
            int t = tid >> 3, hh = tid & 7;
            int qb = t*32 + hh*4, kb = hh*4;
            float4 q0 = q4[qb], q1 = q4[qb+1], q2 = q4[qb+2], q3 = q4[qb+3];
            float s[NTOK];
            float mx = -1e30f;
            #pragma unroll
            for (int m = 0; m < NTOK; m++) if (m < n) {
                float4 a0 = k4[m*32+kb],   a1 = k4[m*32+kb+1];
                float4 a2 = k4[m*32+kb+2], a3 = k4[m*32+kb+3];
                float p = q0.x*a0.x + q0.y*a0.y + q0.z*a0.z + q0.w*a0.w
                        + q1.x*a1.x + q1.y*a1.y + q1.z*a1.z + q1.w*a1.w
                        + q2.x*a2.x + q2.y*a2.y + q2.z*a2.z + q2.w*a2.w
                        + q3.x*a3.x + q3.y*a3.y + q3.z*a3.z + q3.w*a3.w;
                p *= 0.25f;
                s[m] = p;
                mx = fmaxf(mx, p);
            }
            float ssum = 0.f;
            #pragma unroll
            for (int m = 0; m < NTOK; m++) if (m < n) {
                float e = expf(s[m]-mx); s[m] = e; ssum += e;
            }
            float inv = 1.f/ssum;
            float o[16];
            #pragma unroll
            for (int j = 0; j < 16; j++) o[j] = 0.f;
            #pragma unroll
            for (int m = 0; m < NTOK; m++) if (m < n) {
                float a = s[m]*inv;
                float4 va = v4[m*32+kb],   vb = v4[m*32+kb+1];
                float4 vc = v4[m*32+kb+2], vd = v4[m*32+kb+3];
                o[0] += a*va.x;  o[1] += a*va.y;  o[2] += a*va.z;  o[3] += a*va.w;
                o[4] += a*vb.x;  o[5] += a*vb.y;  o[6] += a*vb.z;  o[7] += a*vb.w;
                o[8] += a*vc.x;  o[9] += a*vc.y;  o[10]+= a*vc.z;  o[11]+= a*vc.w;
                o[12]+= a*vd.x;  o[13]+= a*vd.y;  o[14]+= a*vd.z;  o[15]+= a*vd.w;
            }
            #pragma unroll
            for (int j = 0; j < 16; j++) outr[j] = o[j];
        }
    }
    __syncthreads();
    if (tid < npairs) {
        float4* aw = (float4*)qs;
        int t = tid >> 3, hh = tid & 7;
        #pragma unroll
        for (int j4 = 0; j4 < 4; j4++)
            aw[t*32 + hh*4 + j4] = make_float4(outr[j4*4], outr[j4*4+1],
                                              outr[j4*4+2], outr[j4*4+3]);
    }
    __syncthreads();

    // ---- output projection + residual + BN partials (group's token half) ----
    float psum = 0.f, psq = 0.f;
    {
        const float4* wo4 = g_wop + l*4096 + f;
        const float4* a4 = (const float4*)qs;
        for (int t0 = tstart; t0 < tend; t0 += 5) {
            float acc[5];
            int base[5];
            #pragma unroll
            for (int u = 0; u < 5; u++) {
                acc[u] = 0.f;
                int t = t0 + u;
                base[u] = ((t < tend) ? t : (tend-1)) * 32;
            }
            for (int j4 = 0; j4 < 32; j4++) {
                float4 w = wo4[j4*128];
                #pragma unroll
                for (int u = 0; u < 5; u++) {
                    float4 a = a4[base[u] + j4];
                    acc[u] += a.x*w.x + a.y*w.y + a.z*w.z + a.w*w.w;
                }
            }
            #pragma unroll
            for (int u = 0; u < 5; u++) {
                int t = t0 + u;
                if (t < tend) {
                    float y = xs[t][f] + acc[u];
                    g_buf1[(size_t)b*NTOK*Dm + t*Dm + f] = y;
                    psum += y; psq += y*y;
                }
            }
        }
    }
    bn_stats_tail256(b, tid, f, g, n, gam, bet, g_bn1s, g_bn1h, &g_cntA, psum, psq, sA, sB);
}

// ---------------- FFN + residual + fused BN2 stats (256 threads) ----------------
__global__ void __launch_bounds__(256, 4) k_ffn(int l,
        const float* __restrict__ b1, const float* __restrict__ b2,
        const float* __restrict__ gam, const float* __restrict__ bet, int n)
{
    __shared__ __align__(16) float us[24][Dm];
    __shared__ __align__(16) float f1s[8][FFd];
    __shared__ float c2[8][2][Dm];
    __shared__ float sA[256], sB[256];
    int b = blockIdx.x, tid = threadIdx.x;
    int f = tid & 127, g = tid >> 7;
    float s1 = g_bn1s[f], h1 = g_bn1h[f];
    #pragma unroll
    for (int t = g*12; t < g*12+12; t++)
        us[t][f] = (t < n) ? (g_buf1[(size_t)b*NTOK*Dm + t*Dm + f]*s1 + h1) : 0.f;
    float bv0 = b1[f], bv1 = b1[128+f], bv2 = b1[256+f], bv3 = b1[384+f];
    float b2v = b2[f];
    float psum = 0.f, psq = 0.f;
    __syncthreads();

    const float4* w1p = g_w1p + l*16384 + f;
    const float4* w2p = g_w2p + l*16384 + f;
    const float4 (*us4)[32] = (const float4 (*)[32])us;

    for (int t0 = 0; t0 < n; t0 += 8) {
        // stage 1: group handles 4 tokens of the 8-chunk, all 4 hidden quadrants
        {
            float a0[4], a1[4], a2[4], a3[4];
            int rb[4];
            #pragma unroll
            for (int u = 0; u < 4; u++) {
                a0[u]=bv0; a1[u]=bv1; a2[u]=bv2; a3[u]=bv3;
                int t = t0 + g*4 + u;
                rb[u] = (t < n) ? t : (n-1);
            }
            for (int d4 = 0; d4 < 32; d4++) {
                float4 xv[4];
                #pragma unroll
                for (int u = 0; u < 4; u++) xv[u] = us4[rb[u]][d4];
                #pragma unroll
                for (int r = 0; r < 4; r++) {
                    float4 w = w1p[(d4*4 + r)*128];
                    #pragma unroll
                    for (int u = 0; u < 4; u++) {
                        float x = (r==0)?xv[u].x:(r==1)?xv[u].y:(r==2)?xv[u].z:xv[u].w;
                        a0[u] += x*w.x; a1[u] += x*w.y; a2[u] += x*w.z; a3[u] += x*w.w;
                    }
                }
            }
            #pragma unroll
            for (int u = 0; u < 4; u++) {
                int uu = g*4 + u;
                f1s[uu][f      ] = fmaxf(a0[u], 0.f);
                f1s[uu][f + 128] = fmaxf(a1[u], 0.f);
                f1s[uu][f + 256] = fmaxf(a2[u], 0.f);
                f1s[uu][f + 384] = fmaxf(a3[u], 0.f);
            }
        }
        __syncthreads();
        // stage 2: split the 512-hidden reduction across groups (64 j4 each)
        {
            float c[8];
            #pragma unroll
            for (int u = 0; u < 8; u++) c[u] = 0.f;
            for (int j4 = g*64; j4 < g*64 + 64; j4++) {
                float4 w = w2p[j4*128];
                #pragma unroll
                for (int u = 0; u < 8; u++) {
                    float4 fv = ((const float4*)f1s[u])[j4];
                    c[u] += fv.x*w.x + fv.y*w.y + fv.z*w.z + fv.w*w.w;
                }
            }
            #pragma unroll
            for (int u = 0; u < 8; u++) c2[u][g][f] = c[u];
        }
        __syncthreads();
        #pragma unroll
        for (int u = 0; u < 4; u++) {
            int t = t0 + g*4 + u;
            if (t < n) {
                int uu = g*4 + u;
                float y = us[t][f] + c2[uu][0][f] + c2[uu][1][f] + b2v;
                g_buf2[(size_t)b*NTOK*Dm + t*Dm + f] = y;
                psum += y; psq += y*y;
            }
        }
        __syncthreads();
    }
    bn_stats_tail256(b, tid, f, g, n, gam, bet, g_bn2s, g_bn2h, &g_cntB, psum, psq, sA, sB);
}

// ---------------- decode step (256 threads) ----------------
__global__ void __launch_bounds__(256, 4) k_decode(int i, int n,
        const float* __restrict__ Wc2, const float* __restrict__ bc2,
        float* __restrict__ out)
{
    __shared__ __align__(16) float es[24][Dm];
    __shared__ __align__(16) float ps[NTOK*384];
    __shared__ __align__(16) float gms[Dm];
    __shared__ __align__(16) float glim[Dm];
    __shared__ float qv[Dm], go[Dm];
    __shared__ float logit_s[NTOK];
    __shared__ float red[256];
    __shared__ float sA[256];
    __shared__ int   sel_s;
    __shared__ float lp_s;
    int b = blockIdx.x, tid = threadIdx.x;
    int f = tid & 127, g = tid >> 7;

    // E = bn2(buf2); g_mean (split rows across groups, combine)
    float s2 = g_bn2s[f], h2 = g_bn2h[f];
    float gsum = 0.f;
    #pragma unroll
    for (int t = g*12; t < g*12+12; t++) {
        float e = (t < n) ? (g_buf2[(size_t)b*NTOK*Dm + t*Dm + f]*s2 + h2) : 0.f;
        es[t][f] = e; gsum += e;
    }
    sA[tid] = gsum;
    __syncthreads();
    if (g == 0) gms[f] = (sA[f] + sA[f+128]) / (float)n;
    __syncthreads();

    const float4* gms4 = (const float4*)gms;

    // q = g_mean @ W_fixed + ctx_q  (split k-range, combine)
    {
        float qa = (g == 0) ? g_ctxq[f] : 0.f;
        const float4* wf = g_wfp + f;
        for (int k4 = g*16; k4 < g*16+16; k4++) {
            float4 gv = gms4[k4];
            float4 w = wf[k4*128];
            qa += gv.x*w.x + gv.y*w.y + gv.z*w.z + gv.w*w.w;
        }
        sA[tid] = qa;
    }
    __syncthreads();
    if (g == 0) qv[f] = sA[f] + sA[f+128];

    // P = E @ W_node (token halves per group, chunks of 5)
    int n0 = (n + 1) >> 1;
    int tstart = g ? n0 : 0;
    int tend   = g ? n  : n0;
    {
        const float4* wn = g_wnp + f;
        const float4 (*es4)[32] = (const float4 (*)[32])es;
        for (int t0 = tstart; t0 < tend; t0 += 5) {
            float a0[5], a1[5], a2[5];
            int rb[5];
            #pragma unroll
            for (int u = 0; u < 5; u++) {
                a0[u]=0.f; a1[u]=0.f; a2[u]=0.f;
                int t = t0 + u;
                rb[u] = (t < tend) ? t : (tend-1);
            }
            for (int d4 = 0; d4 < 32; d4++) {
                float4 xv[5];
                #pragma unroll
                for (int u = 0; u < 5; u++) xv[u] = es4[rb[u]][d4];
                #pragma unroll
                for (int r = 0; r < 4; r++) {
                    float4 w = wn[(d4*4 + r)*128];
                    #pragma unroll
                    for (int u = 0; u < 5; u++) {
                        float x = (r==0)?xv[u].x:(r==1)?xv[u].y:(r==2)?xv[u].z:xv[u].w;
                        a0[u] += x*w.x; a1[u] += x*w.y; a2[u] += x*w.z;
                    }
                }
            }
            #pragma unroll
            for (int u = 0; u < 5; u++) {
                int t = t0 + u;
                if (t < tend) {
                    ps[t*384 + f      ] = a0[u];
                    ps[t*384 + f + 128] = a1[u];
                    ps[t*384 + f + 256] = a2[u];
                }
            }
        }
    }
    __syncthreads();

    // glimpse attention on first 128 threads (tid = h*16+kd)
    if (tid < 128) {
        float qh = qv[tid];
        float sc[NTOK];
        float mx = -1e30f;
        #pragma unroll
        for (int m = 0; m < NTOK; m++) if (m < n) {
            float p = qh * ps[m*384 + tid];
            #pragma unroll
            for (int o = 8; o > 0; o >>= 1) p += __shfl_xor_sync(0xffffffffu, p, o, 16);
            p *= 0.25f;
            sc[m] = p;
            mx = fmaxf(mx, p);
        }
        float ssum = 0.f;
        #pragma unroll
        for (int m = 0; m < NTOK; m++) if (m < n) {
            float e = expf(sc[m]-mx); sc[m] = e; ssum += e;
        }
        float gl = 0.f;
        #pragma unroll
        for (int m = 0; m < NTOK; m++) if (m < n)
            gl += sc[m]*ps[m*384 + 128 + tid];
        glim[tid] = gl/ssum;
    }
    __syncthreads();
    // go = glimpse @ W_out (split k-range, combine)
    {
        float gg = 0.f;
        const float4* wo = g_woutp + f;
        const float4* gl4 = (const float4*)glim;
        for (int k4 = g*16; k4 < g*16+16; k4++) {
            float4 gv = gl4[k4];
            float4 w = wo[k4*128];
            gg += gv.x*w.x + gv.y*w.y + gv.z*w.z + gv.w*w.w;
        }
        sA[tid] = gg;
    }
    __syncthreads();
    if (g == 0) go[f] = sA[f] + sA[f+128];
    __syncthreads();
    // logits per token (8 warps now)
    {
        int w = tid >> 5, lane = tid & 31;
        for (int t = w; t < n; t += 8) {
            float p = 0.f;
            #pragma unroll
            for (int r = 0; r < 4; r++)
                p += go[lane + 32*r]*ps[t*384 + 256 + lane + 32*r];
            #pragma unroll
            for (int o = 16; o > 0; o >>= 1) p += __shfl_xor_sync(0xffffffffu, p, o);
            if (lane == 0)
                logit_s[t] = tanhf(p * 0.08838834764831845f) * 10.f;
        }
    }
    __syncthreads();
    // log_softmax + argmax (first-max tie rule) on warp 0
    if (tid < 32) {
        float v = (tid < n) ? logit_s[tid] : -1e30f;
        float m = v;
        #pragma unroll
        for (int o = 16; o > 0; o >>= 1) m = fmaxf(m, __shfl_xor_sync(0xffffffffu, m, o));
        int idx = (tid < n && v == m) ? tid : (1 << 30);
        #pragma unroll
        for (int o = 16; o > 0; o >>= 1) idx = min(idx, __shfl_xor_sync(0xffffffffu, idx, o));
        float e = (tid < n) ? expf(v - m) : 0.f;
        float se = e;
        #pragma unroll
        for (int o = 16; o > 0; o >>= 1) se += __shfl_xor_sync(0xffffffffu, se, o);
        if (tid == 0) { sel_s = idx; lp_s = logit_s[idx] - m - logf(se); }
    }
    __syncthreads();
    int sel = sel_s;

    // value head: 2 hidden units per thread (j = tid, tid+256)
    {
        float part = 0.f;
        #pragma unroll
        for (int r = 0; r < 2; r++) {
            int j = tid + 256*r;
            float acc = g_cph[j];
            const float4* wc = g_wc1p + j;
            for (int k4 = 0; k4 < 32; k4++) {
                float4 gv = gms4[k4];
                float4 w = wc[k4*512];
                acc += gv.x*w.x + gv.y*w.y + gv.z*w.z + gv.w*w.w;
            }
            part += fmaxf(acc, 0.f)*Wc2[j];
        }
        red[tid] = part;
    }
    __syncthreads();
    for (int st = 128; st > 0; st >>= 1) {
        if (tid < st) red[tid] += red[tid+st];
        __syncthreads();
    }

    // outputs + state (thread 0)
    if (tid == 0) {
        float val = red[0] + bc2[0];
        float cx = g_crd[b*NTOK*2 + sel*2], cy = g_crd[b*NTOK*2 + sel*2 + 1];
        float ir = 0.f;
        if (i == 0) {
            g_first[2*b] = cx; g_first[2*b+1] = cy;
        } else {
            float dx = cx - g_prev[2*b], dy = cy - g_prev[2*b+1];
            ir = -sqrtf(dx*dx + dy*dy);
        }
        g_prev[2*b] = cx; g_prev[2*b+1] = cy;
        int node = g_nidx[b*NTOK + sel];
        g_tours[b*NTOK + i] = node;
        out[             b*NTOK + i] = lp_s;
        out[Bsz*NTOK   + b*NTOK + i] = ir;
        out[2*Bsz*NTOK + b*NTOK + i] = val;
        out[3*Bsz*NTOK + 2*Bsz + b*NTOK + i] = (float)node;
    }
    __syncthreads();

    // compaction: reg-staged parallel shift of g_x rows (both groups, interleaved),
    // then serial crd/nidx by dedicated threads
    if (i < NTOK-1) {
        float tmp[10];
        int cnt = 0;
        for (int t = sel + g; t < n-1; t += 2)
            tmp[cnt++] = g_x[(size_t)b*NTOK*Dm + (t+1)*Dm + f];
        __syncthreads();
        cnt = 0;
        for (int t = sel + g; t < n-1; t += 2)
            g_x[(size_t)b*NTOK*Dm + t*Dm + f] = tmp[cnt++];
        if (tid < 2)
            for (int t = sel; t < n-1; t++)
                g_crd[b*NTOK*2 + t*2 + tid] = g_crd[b*NTOK*2 + (t+1)*2 + tid];
        if (tid == 0)
            for (int t = sel; t < n-1; t++)
                g_nidx[b*NTOK + t] = g_nidx[b*NTOK + t+1];
    }
}

// ---------------- final: tour cost + reward_final ----------------
__global__ void k_final(const float* __restrict__ coords, float* __restrict__ out)
{
    int b = blockIdx.x*blockDim.x + threadIdx.x;
    if (b >= Bsz) return;
    const int* tb = g_tours + b*NTOK;
    const float* cb = coords + b*NTOK*2;
    float x0 = cb[tb[0]*2], y0 = cb[tb[0]*2 + 1];
    float px = x0, py = y0;
    float cost = 0.f;
    for (int t = 1; t < NTOK; t++) {
        float x = cb[tb[t]*2], y = cb[tb[t]*2 + 1];
        float dx = x - px, dy = y - py;
        cost += sqrtf(dx*dx + dy*dy);
        px = x; py = y;
    }
    {
        float dx = x0 - px, dy = y0 - py;
        cost += sqrtf(dx*dx + dy*dy);
    }
    out[3*Bsz*NTOK + b] = cost;
    float fx = g_first[2*b] - g_prev[2*b];
    float fy = g_first[2*b+1] - g_prev[2*b+1];
    out[3*Bsz*NTOK + Bsz + b] = -sqrtf(fx*fx + fy*fy);
}

// ---------------- host ----------------
extern "C" void kernel_launch(void* const* d_in, const int* in_sizes, int n_in,
                              void* d_out, int out_size)
{
    const float* coords  = (const float*)d_in[0];
    const float* Wi      = (const float*)d_in[1];
    const float* bi      = (const float*)d_in[2];
    const float* W_ph    = (const float*)d_in[3];
    const float* eWq     = (const float*)d_in[4];
    const float* eWk     = (const float*)d_in[5];
    const float* eWv     = (const float*)d_in[6];
    const float* eWo     = (const float*)d_in[7];
    const float* eg1     = (const float*)d_in[8];
    const float* eb1     = (const float*)d_in[9];
    const float* effW1   = (const float*)d_in[10];
    const float* effb1   = (const float*)d_in[11];
    const float* effW2   = (const float*)d_in[12];
    const float* effb2   = (const float*)d_in[13];
    const float* eg2     = (const float*)d_in[14];
    const float* eb2     = (const float*)d_in[15];
    const float* W_node  = (const float*)d_in[16];
    const float* W_fixed = (const float*)d_in[17];
    const float* W_step  = (const float*)d_in[18];
    const float* W_out   = (const float*)d_in[19];
    const float* Wc1     = (const float*)d_in[20];
    const float* bc1     = (const float*)d_in[21];
    const float* Wc2     = (const float*)d_in[22];
    const float* bc2     = (const float*)d_in[23];
    float* out = (float*)d_out;

    k_pack<<<784, 256>>>(eWq, eWk, eWv, eWo, effW1, effW2,
                         W_node, W_fixed, W_out, Wc1);
    k_embed<<<Bsz, 128>>>(coords, Wi, bi);
    k_setup<<<1, 512>>>(W_ph, W_step, Wc1, bc1);

    for (int i = 0; i < NTOK; i++) {
        int n = NTOK - i;
        for (int l = 0; l < 3; l++) {
            k_mha<<<Bsz, 256>>>(l == 0 ? 0 : 1, l, eg1 + l*Dm, eb1 + l*Dm, n);
            k_ffn<<<Bsz, 256>>>(l, effb1 + l*FFd, effb2 + l*Dm,
                                eg2 + l*Dm, eb2 + l*Dm, n);
        }
        k_decode<<<Bsz, 256>>>(i, n, Wc2, bc2, out);
    }
    k_final<<<2, 256>>>(coords, out);
}